// round 14
// baseline (speedup 1.0000x reference)
#include <cuda_runtime.h>
#include <cuda_bf16.h>
#include <cuda_fp16.h>
#include <math.h>

#define BB 8
#define NN 4096
#define CINC 128
#define COUTC 256
#define SSP 1024
#define KNB 24
#define TCHC 256
#define MTOK 32
#define NROWS (BB*SSP*KNB)     /* 196608 */
#define NGRP  (BB*SSP)         /* 8192 */
#define NPTS  (BB*NN)          /* 32768 */
#define BN_SCALE 0.9999950000374997f

// weight-pool offsets (halves)
#define WOFF_PROJ 0
#define WOFF_L1   32768
#define WOFF_L2   98304
#define WOFF_C1   163840
#define WOFF_C2   229376
#define WOFF_K    294912
#define WOFF_V    360448
#define WPOOL_N   425984

// ------------------------- device scratch ------------------------------------
__device__ float  g_xT[(size_t)BB*NN*CINC];
__device__ int    g_fps[BB*SSP];
__device__ int    g_knn[NROWS];
__device__ float  g_y [(size_t)NPTS*COUTC];
__device__ __half g_h0h[(size_t)NROWS*COUTC];
__device__ __half g_rh [(size_t)NROWS*COUTC];
__device__ __half g_wh[WPOOL_N];
__device__ float  g_f [(size_t)NGRP*COUTC];
__device__ float  g_c1[(size_t)NGRP*COUTC];
__device__ float  g_f2[(size_t)NGRP*COUTC];
__device__ float  g_kk[(size_t)NGRP*TCHC];
__device__ float  g_v [(size_t)NGRP*TCHC];
__device__ float  g_q [BB*MTOK*TCHC];
__device__ float  g_av[BB*MTOK*TCHC];
__device__ float  g_t1[BB*MTOK*TCHC];
__device__ float  g_hn[BB*MTOK*TCHC];
__device__ float  g_qkvb[BB*MTOK*3*TCHC];
__device__ float  g_mo[BB*MTOK*TCHC];
__device__ float  g_t2[BB*MTOK*TCHC];
__device__ float  g_ff[BB*MTOK*2*TCHC];

#define ID_H0 0
#define ID_R 1
#define ID_F 2
#define ID_C1 3
#define ID_F2 4
#define ID_KK 5
#define ID_V 6
#define ID_Q 7
#define ID_AV 8
#define ID_T1 9
#define ID_HN 10
#define ID_QKVB 11
#define ID_MO 12
#define ID_T2 13
#define ID_FF 14
#define ID_Y 15
#define ID_XT 16

__device__ __forceinline__ float* buf_ptr(int id){
    switch(id){
        case ID_F:  return g_f;    case ID_C1: return g_c1;
        case ID_F2: return g_f2;   case ID_KK: return g_kk;
        case ID_V:  return g_v;    case ID_Q:  return g_q;
        case ID_AV: return g_av;   case ID_T1: return g_t1;
        case ID_HN: return g_hn;   case ID_QKVB: return g_qkvb;
        case ID_MO: return g_mo;   case ID_T2: return g_t2;
        case ID_FF: return g_ff;   case ID_Y:  return g_y;
        case ID_XT: return g_xT;
    }
    return nullptr;
}
__device__ __forceinline__ __half* buf_ptr_h(int id){
    if (id == ID_H0) return g_h0h;
    if (id == ID_R)  return g_rh;
    return nullptr;
}

__device__ __forceinline__ float gelu_f(float x){
    return 0.5f * x * (1.0f + erff(x * 0.7071067811865476f));
}

__device__ __forceinline__ void mma_f16(float* d, const unsigned* a, const unsigned* b){
    asm volatile(
        "mma.sync.aligned.m16n8k16.row.col.f32.f16.f16.f32 "
        "{%0,%1,%2,%3}, {%4,%5,%6,%7}, {%8,%9}, {%0,%1,%2,%3};\n"
        : "+f"(d[0]), "+f"(d[1]), "+f"(d[2]), "+f"(d[3])
        : "r"(a[0]), "r"(a[1]), "r"(a[2]), "r"(a[3]), "r"(b[0]), "r"(b[1]));
}

// ------------------------- weight conversion (once per launch) -----------------
__global__ void cvt_w_kernel(const float* __restrict__ src, int off, int n){
    int i = blockIdx.x * 256 + threadIdx.x;
    if (i < n) g_wh[off + i] = __float2half_rn(src[i]);
}

// ------------------------- transpose x [B,128,4096]->[B,4096,128] -------------
__global__ void transpose_x_kernel(const float* __restrict__ x){
    __shared__ float tile[32][33];
    int n0 = blockIdx.x << 5, c0 = blockIdx.y << 5, b = blockIdx.z;
    int tx = threadIdx.x, ty = threadIdx.y;
    tile[ty][tx] = x[((size_t)(b*CINC + c0 + ty)) * NN + n0 + tx];
    __syncthreads();
    g_xT[((size_t)((b << 12) + n0 + ty)) * CINC + c0 + tx] = tile[tx][ty];
}

// ------------------------- FPS ------------------------------------------------
__global__ void fps_kernel(const float* __restrict__ xyz, const int* __restrict__ far0,
                           float* __restrict__ onxyz){
    __shared__ unsigned sd[32];
    __shared__ int      si[32];
    __shared__ float c3[3];
    __shared__ int s_far;
    int b = blockIdx.x, tid = threadIdx.x;
    int lane = tid & 31, w = tid >> 5;
    float px[4], py[4], pz[4], dmin[4];
#pragma unroll
    for (int i = 0; i < 4; i++){
        int j = (i << 10) + tid;
        const float* p = xyz + ((size_t)((b << 12) + j)) * 3;
        px[i] = p[0]; py[i] = p[1]; pz[i] = p[2];
        dmin[i] = 1e10f;
    }
    if (tid == 0){
        int f = far0[b]; s_far = f;
        const float* p = xyz + ((size_t)((b << 12) + f)) * 3;
        c3[0] = p[0]; c3[1] = p[1]; c3[2] = p[2];
    }
    __syncthreads();
    for (int it = 0; it < SSP; it++){
        float cx = c3[0], cy = c3[1], cz = c3[2];
        if (tid == 0){
            g_fps[(b << 10) + it] = s_far;
            float* o = onxyz + ((size_t)((b << 10) + it)) * 3;
            o[0] = cx; o[1] = cy; o[2] = cz;
        }
        unsigned um = 0u;
#pragma unroll
        for (int i = 0; i < 4; i++){
            float dx = px[i] - cx, dy = py[i] - cy, dz = pz[i] - cz;
            float d = dx*dx + dy*dy + dz*dz;
            dmin[i] = fminf(dmin[i], d);
            unsigned u = __float_as_uint(dmin[i]);
            if (u > um) um = u;
        }
        unsigned wm = __reduce_max_sync(0xffffffffu, um);
        int cand = 0x7FFFFFFF;
#pragma unroll
        for (int i = 0; i < 4; i++){
            if (__float_as_uint(dmin[i]) == wm){
                int j = (i << 10) + tid;
                if (j < cand) cand = j;
            }
        }
        int wj = (int)__reduce_min_sync(0xffffffffu, (unsigned)cand);
        if (lane == 0){ sd[w] = wm; si[w] = wj; }
        __syncthreads();
        if (tid < 32){
            unsigned v = sd[tid]; int idx = si[tid];
            unsigned m = __reduce_max_sync(0xffffffffu, v);
            int c2 = (v == m) ? idx : 0x7FFFFFFF;
            int nf = (int)__reduce_min_sync(0xffffffffu, (unsigned)c2);
            if (tid == 0){
                s_far = nf;
                const float* p = xyz + ((size_t)((b << 12) + nf)) * 3;
                c3[0] = p[0]; c3[1] = p[1]; c3[2] = p[2];
            }
        }
        __syncthreads();
    }
}

// ------------------------- KNN: REDUX top-24 with grouped rescan ---------------
__global__ void knn_kernel(const float* __restrict__ nxyz, const float* __restrict__ xyz){
    int cid = blockIdx.x, tid = threadIdx.x;
    int lane = tid & 31, w = tid >> 5;
    int b = cid >> 10;
    float cx = nxyz[(size_t)cid*3+0], cy = nxyz[(size_t)cid*3+1], cz = nxyz[(size_t)cid*3+2];
    float d[32];
#pragma unroll
    for (int i = 0; i < 32; i++){
        int j = (w << 10) + (i << 5) + lane;
        const float* p = xyz + ((size_t)((b << 12) + j)) * 3;
        float dx = p[0]-cx, dy = p[1]-cy, dz = p[2]-cz;
        d[i] = dx*dx + dy*dy + dz*dz;
    }
    __shared__ unsigned cd[4*KNB];
    __shared__ int      ci[4*KNB];

    float gm[4]; int gi[4];
#pragma unroll
    for (int g = 0; g < 4; g++){
        gm[g] = 3.4e38f; gi[g] = g*8;
#pragma unroll
        for (int k = 0; k < 8; k++){
            int i = g*8 + k;
            if (d[i] < gm[g]){ gm[g] = d[i]; gi[g] = i; }
        }
    }
    unsigned consumed = 0u;
#pragma unroll 1
    for (int r = 0; r < KNB; r++){
        float bd = gm[0]; int bi = gi[0];
        if (gm[1] < bd){ bd = gm[1]; bi = gi[1]; }
        if (gm[2] < bd){ bd = gm[2]; bi = gi[2]; }
        if (gm[3] < bd){ bd = gm[3]; bi = gi[3]; }
        unsigned dbits = __float_as_uint(bd);
        unsigned wmin = __reduce_min_sync(0xffffffffu, dbits);
        int myidx = (dbits == wmin) ? ((w << 10) + (bi << 5) + lane) : 0x7FFFFFFF;
        int widx = (int)__reduce_min_sync(0xffffffffu, (unsigned)myidx);
        if (lane == 0){ cd[w*KNB + r] = wmin; ci[w*KNB + r] = widx; }
        if (myidx == widx){
            consumed |= 1u << bi;
            int g = bi >> 3;
            if (g == 0){
                gm[0] = 3.4e38f; gi[0] = 0;
#pragma unroll
                for (int k = 0; k < 8; k++)
                    if (!((consumed >> k) & 1u) && d[k] < gm[0]){ gm[0] = d[k]; gi[0] = k; }
            } else if (g == 1){
                gm[1] = 3.4e38f; gi[1] = 8;
#pragma unroll
                for (int k = 8; k < 16; k++)
                    if (!((consumed >> k) & 1u) && d[k] < gm[1]){ gm[1] = d[k]; gi[1] = k; }
            } else if (g == 2){
                gm[2] = 3.4e38f; gi[2] = 16;
#pragma unroll
                for (int k = 16; k < 24; k++)
                    if (!((consumed >> k) & 1u) && d[k] < gm[2]){ gm[2] = d[k]; gi[2] = k; }
            } else {
                gm[3] = 3.4e38f; gi[3] = 24;
#pragma unroll
                for (int k = 24; k < 32; k++)
                    if (!((consumed >> k) & 1u) && d[k] < gm[3]){ gm[3] = d[k]; gi[3] = k; }
            }
        }
    }
    __syncthreads();

    if (w == 0){
        unsigned kd[3]; int ki[3];
#pragma unroll
        for (int s = 0; s < 3; s++){ kd[s] = cd[lane + 32*s]; ki[s] = ci[lane + 32*s]; }
#pragma unroll 1
        for (int r = 0; r < KNB; r++){
            unsigned lmd = kd[0]; int lmi = ki[0];
            if (kd[1] < lmd || (kd[1] == lmd && ki[1] < lmi)){ lmd = kd[1]; lmi = ki[1]; }
            if (kd[2] < lmd || (kd[2] == lmd && ki[2] < lmi)){ lmd = kd[2]; lmi = ki[2]; }
            unsigned wmin = __reduce_min_sync(0xffffffffu, lmd);
            int myidx = (lmd == wmin) ? lmi : 0x7FFFFFFF;
            int widx = (int)__reduce_min_sync(0xffffffffu, (unsigned)myidx);
            if (lane == 0) g_knn[(size_t)cid*KNB + r] = widx;
#pragma unroll
            for (int s = 0; s < 3; s++)
                if (ki[s] == widx){ kd[s] = 0xFFFFFFFFu; ki[s] = 0x7FFFFFFF; }
        }
    }
}

// ------------------------- edge combine: h0 = fp16(gelu(bn(y[nbr]-y[ctr]))) ----
__global__ void edge_kernel(const float* __restrict__ gproj, const float* __restrict__ bproj){
    int r = blockIdx.x * 4 + (threadIdx.x >> 6);
    int c4 = threadIdx.x & 63;
    int cid = r / KNB;
    int b = cid >> 10;
    int nbr = (b << 12) + g_knn[r];
    int ctr = (b << 12) + g_fps[cid];
    float4 a = ((const float4*)(g_y + (size_t)nbr * COUTC))[c4];
    float4 cc = ((const float4*)(g_y + (size_t)ctr * COUTC))[c4];
    int c = c4 << 2;
    float4 ga = *(const float4*)(gproj + c);
    float4 be = *(const float4*)(bproj + c);
    float o0 = gelu_f(fmaf(a.x - cc.x, ga.x * BN_SCALE, be.x));
    float o1 = gelu_f(fmaf(a.y - cc.y, ga.y * BN_SCALE, be.y));
    float o2 = gelu_f(fmaf(a.z - cc.z, ga.z * BN_SCALE, be.z));
    float o3 = gelu_f(fmaf(a.w - cc.w, ga.w * BN_SCALE, be.w));
    __half2* dst = (__half2*)(g_h0h + (size_t)r * COUTC + c);
    dst[0] = __floats2half2_rn(o0, o1);
    dst[1] = __floats2half2_rn(o2, o3);
}

// ------------------------- fp16 tensor-core NT GEMM ----------------------------
// a_half: A from half buffer (raw copy). w_off>=0: W from pre-converted half pool.
#define HST 24
__global__ void __launch_bounds__(256)
gemm_tc(const float* __restrict__ Aext, int Aid,
        const float* __restrict__ W, int w_off,
        float* __restrict__ Cext, int Cid,
        int Kdim, int Ncols,
        const float* __restrict__ gamma, const float* __restrict__ beta,
        const float* __restrict__ resext, int resid,
        int act, int a_half, int c_half, int res_half)
{
    __shared__ __align__(16) __half As[2][128][HST];
    __shared__ __align__(16) __half Bs[2][128][HST];
    const float* A = (Aid >= 0 && !a_half) ? buf_ptr(Aid) : Aext;
    const __half* Ah = a_half ? buf_ptr_h(Aid) : nullptr;
    float* C = (Cid >= 0 && !c_half) ? buf_ptr(Cid) : Cext;
    __half* Ch = c_half ? buf_ptr_h(Cid) : nullptr;
    const float* res = (resid >= 0 && !res_half) ? buf_ptr(resid) : resext;
    const __half* resh = res_half ? buf_ptr_h(resid) : nullptr;

    const int tid = threadIdx.x;
    const int r0 = blockIdx.y * 128;
    const int n0 = blockIdx.x * 128;

    const int arow = tid >> 1;
    const int ak0  = (tid & 1) * 8;
    const float* pA = a_half ? nullptr : (A + (size_t)(r0 + arow) * Kdim + ak0);
    const __half* pAh = a_half ? (Ah + (size_t)(r0 + arow) * Kdim + ak0) : nullptr;
    const float* pW = (w_off < 0) ? (W + (size_t)(n0 + arow) * Kdim + ak0) : nullptr;
    const __half* pWh = (w_off >= 0) ? (g_wh + w_off + (size_t)(n0 + arow) * Kdim + ak0) : nullptr;

    const int wid = tid >> 5, lane = tid & 31;
    const int wm0 = (wid & 1) * 64;
    const int wn0 = (wid >> 1) * 32;
    const int lr = lane >> 2;
    const int lc = lane & 3;

    float acc[4][4][4];
#pragma unroll
    for (int i = 0; i < 4; i++)
#pragma unroll
        for (int j = 0; j < 4; j++)
#pragma unroll
            for (int v = 0; v < 4; v++) acc[i][j][v] = 0.f;

    const int KT = Kdim >> 4;

    {
        unsigned* da = (unsigned*)&As[0][arow][ak0];
        if (a_half){
            uint4 v = *(const uint4*)(pAh);
            da[0] = v.x; da[1] = v.y; da[2] = v.z; da[3] = v.w;
        } else {
            float4 a0 = *(const float4*)(pA), a1 = *(const float4*)(pA + 4);
            __half2* dh = (__half2*)da;
            dh[0] = __floats2half2_rn(a0.x, a0.y); dh[1] = __floats2half2_rn(a0.z, a0.w);
            dh[2] = __floats2half2_rn(a1.x, a1.y); dh[3] = __floats2half2_rn(a1.z, a1.w);
        }
        unsigned* db = (unsigned*)&Bs[0][arow][ak0];
        if (w_off >= 0){
            uint4 v = *(const uint4*)(pWh);
            db[0] = v.x; db[1] = v.y; db[2] = v.z; db[3] = v.w;
        } else {
            float4 b0 = *(const float4*)(pW), b1 = *(const float4*)(pW + 4);
            __half2* dh = (__half2*)db;
            dh[0] = __floats2half2_rn(b0.x, b0.y); dh[1] = __floats2half2_rn(b0.z, b0.w);
            dh[2] = __floats2half2_rn(b1.x, b1.y); dh[3] = __floats2half2_rn(b1.z, b1.w);
        }
    }
    __syncthreads();

    for (int kt = 0; kt < KT; kt++){
        int p = kt & 1;
        float4 na0, na1, nb0, nb1;
        uint4 nah, nwh;
        bool more = (kt + 1 < KT);
        if (more){
            int ko = (kt + 1) << 4;
            if (a_half) nah = *(const uint4*)(pAh + ko);
            else { na0 = *(const float4*)(pA + ko); na1 = *(const float4*)(pA + ko + 4); }
            if (w_off >= 0) nwh = *(const uint4*)(pWh + ko);
            else { nb0 = *(const float4*)(pW + ko); nb1 = *(const float4*)(pW + ko + 4); }
        }
        {
            unsigned afr[4][4], bfr[4][2];
#pragma unroll
            for (int mt = 0; mt < 4; mt++){
                int r = wm0 + mt*16 + lr;
                afr[mt][0] = *(const unsigned*)&As[p][r][2*lc];
                afr[mt][1] = *(const unsigned*)&As[p][r+8][2*lc];
                afr[mt][2] = *(const unsigned*)&As[p][r][2*lc+8];
                afr[mt][3] = *(const unsigned*)&As[p][r+8][2*lc+8];
            }
#pragma unroll
            for (int nt = 0; nt < 4; nt++){
                int n = wn0 + nt*8 + lr;
                bfr[nt][0] = *(const unsigned*)&Bs[p][n][2*lc];
                bfr[nt][1] = *(const unsigned*)&Bs[p][n][2*lc+8];
            }
#pragma unroll
            for (int mt = 0; mt < 4; mt++)
#pragma unroll
                for (int nt = 0; nt < 4; nt++)
                    mma_f16(acc[mt][nt], afr[mt], bfr[nt]);
        }
        if (more){
            int q = 1 - p;
            unsigned* da = (unsigned*)&As[q][arow][ak0];
            if (a_half){
                da[0] = nah.x; da[1] = nah.y; da[2] = nah.z; da[3] = nah.w;
            } else {
                __half2* dh = (__half2*)da;
                dh[0] = __floats2half2_rn(na0.x, na0.y); dh[1] = __floats2half2_rn(na0.z, na0.w);
                dh[2] = __floats2half2_rn(na1.x, na1.y); dh[3] = __floats2half2_rn(na1.z, na1.w);
            }
            unsigned* db = (unsigned*)&Bs[q][arow][ak0];
            if (w_off >= 0){
                db[0] = nwh.x; db[1] = nwh.y; db[2] = nwh.z; db[3] = nwh.w;
            } else {
                __half2* dh = (__half2*)db;
                dh[0] = __floats2half2_rn(nb0.x, nb0.y); dh[1] = __floats2half2_rn(nb0.z, nb0.w);
                dh[2] = __floats2half2_rn(nb1.x, nb1.y); dh[3] = __floats2half2_rn(nb1.z, nb1.w);
            }
        }
        __syncthreads();
    }

#pragma unroll
    for (int mt = 0; mt < 4; mt++){
#pragma unroll
        for (int nt = 0; nt < 4; nt++){
            int cb = n0 + wn0 + nt*8 + lc*2;
            float ga0 = 0.f, ga1 = 0.f, be0 = 0.f, be1 = 0.f;
            if (gamma){
                ga0 = gamma[cb] * BN_SCALE;   be0 = beta[cb];
                ga1 = gamma[cb+1] * BN_SCALE; be1 = beta[cb+1];
            }
#pragma unroll
            for (int half = 0; half < 2; half++){
                int r = r0 + wm0 + mt*16 + lr + half*8;
                float y0 = acc[mt][nt][half*2+0];
                float y1 = acc[mt][nt][half*2+1];
                if (gamma){ y0 = fmaf(y0, ga0, be0); y1 = fmaf(y1, ga1, be1); }
                if (res_half){
                    float2 rv = __half22float2(*(const __half2*)(resh + (size_t)r * Ncols + cb));
                    y0 += rv.x; y1 += rv.y;
                } else if (res){
                    y0 += res[(size_t)r * Ncols + cb];
                    y1 += res[(size_t)r * Ncols + cb + 1];
                }
                if (act){ y0 = gelu_f(y0); y1 = gelu_f(y1); }
                if (c_half){
                    *(__half2*)(Ch + (size_t)r * Ncols + cb) = __floats2half2_rn(y0, y1);
                } else {
                    C[(size_t)r * Ncols + cb]     = y0;
                    C[(size_t)r * Ncols + cb + 1] = y1;
                }
            }
        }
    }
}

// ------------------------- fp32 NT GEMM (small token GEMMs) --------------------
__global__ void gemm_nt(const float* __restrict__ Aext, int Aid,
                        const float* __restrict__ W,
                        float* __restrict__ Cext, int Cid,
                        int Kdim, int Ncols,
                        const float* __restrict__ gamma, const float* __restrict__ beta,
                        const float* __restrict__ resext, int resid,
                        int act)
{
    __shared__ __align__(16) float As[16][68];
    __shared__ __align__(16) float Ws[16][68];
    const float* A = (Aid >= 0) ? buf_ptr(Aid) : Aext;
    float* C = (Cid >= 0) ? buf_ptr(Cid) : Cext;
    const float* res = (resid >= 0) ? buf_ptr(resid) : resext;
    const int tid = threadIdx.x;
    const int r0 = blockIdx.y * 64;
    const int n0 = blockIdx.x * 64;
    const int lrow = tid >> 2;
    const int lk4  = (tid & 3) << 2;
    const float* pA = A + (size_t)(r0 + lrow) * Kdim + lk4;
    const float* pW = W + (size_t)(n0 + lrow) * Kdim + lk4;
    const int tm0 = (tid & 15) << 2;
    const int tn0 = (tid >> 4) << 2;
    float acc[4][4];
#pragma unroll
    for (int i = 0; i < 4; i++)
#pragma unroll
        for (int j = 0; j < 4; j++) acc[i][j] = 0.f;

    for (int k0 = 0; k0 < Kdim; k0 += 16){
        float4 av = *(const float4*)(pA + k0);
        float4 wv = *(const float4*)(pW + k0);
        __syncthreads();
        As[lk4+0][lrow]=av.x; As[lk4+1][lrow]=av.y; As[lk4+2][lrow]=av.z; As[lk4+3][lrow]=av.w;
        Ws[lk4+0][lrow]=wv.x; Ws[lk4+1][lrow]=wv.y; Ws[lk4+2][lrow]=wv.z; Ws[lk4+3][lrow]=wv.w;
        __syncthreads();
#pragma unroll
        for (int k = 0; k < 16; k++){
            float4 a4 = *(const float4*)&As[k][tm0];
            float4 w4 = *(const float4*)&Ws[k][tn0];
            acc[0][0]=fmaf(a4.x,w4.x,acc[0][0]); acc[0][1]=fmaf(a4.x,w4.y,acc[0][1]);
            acc[0][2]=fmaf(a4.x,w4.z,acc[0][2]); acc[0][3]=fmaf(a4.x,w4.w,acc[0][3]);
            acc[1][0]=fmaf(a4.y,w4.x,acc[1][0]); acc[1][1]=fmaf(a4.y,w4.y,acc[1][1]);
            acc[1][2]=fmaf(a4.y,w4.z,acc[1][2]); acc[1][3]=fmaf(a4.y,w4.w,acc[1][3]);
            acc[2][0]=fmaf(a4.z,w4.x,acc[2][0]); acc[2][1]=fmaf(a4.z,w4.y,acc[2][1]);
            acc[2][2]=fmaf(a4.z,w4.z,acc[2][2]); acc[2][3]=fmaf(a4.z,w4.w,acc[2][3]);
            acc[3][0]=fmaf(a4.w,w4.x,acc[3][0]); acc[3][1]=fmaf(a4.w,w4.y,acc[3][1]);
            acc[3][2]=fmaf(a4.w,w4.z,acc[3][2]); acc[3][3]=fmaf(a4.w,w4.w,acc[3][3]);
        }
    }
#pragma unroll
    for (int i = 0; i < 4; i++){
        int r = r0 + tm0 + i;
#pragma unroll
        for (int j = 0; j < 4; j++){
            int c = n0 + tn0 + j;
            float y = acc[i][j];
            if (gamma) y = fmaf(y, gamma[c] * BN_SCALE, beta[c]);
            if (res)   y += res[(size_t)r * Ncols + c];
            if (act)   y = gelu_f(y);
            C[(size_t)r * Ncols + c] = y;
        }
    }
}

// ------------------------- maxpool over K neighbors ----------------------------
__global__ void maxpool_kernel(){
    int gidx = blockIdx.x, c = threadIdx.x;
    const __half* p = g_h0h + (size_t)gidx * KNB * COUTC + c;
    float m = -3.4e38f;
#pragma unroll
    for (int j = 0; j < KNB; j++) m = fmaxf(m, __half2float(p[(size_t)j * COUTC]));
    g_f[(size_t)gidx * COUTC + c] = m;
}

// ------------------------- transpose f2 [B,S,C]->[B,C,S] into out --------------
__global__ void transpose_f_kernel(float* __restrict__ out){
    __shared__ float tile[32][33];
    int s0 = blockIdx.x << 5, c0 = blockIdx.y << 5, b = blockIdx.z;
    int tx = threadIdx.x, ty = threadIdx.y;
    tile[ty][tx] = g_f2[((size_t)((b << 10) + s0 + ty)) * COUTC + c0 + tx];
    __syncthreads();
    out[((size_t)(b * COUTC + c0 + ty) << 10) + s0 + tx] = tile[tx][ty];
}

// ------------------------- Local2Former cross-attention ------------------------
__global__ void l2f_attn_kernel(){
    __shared__ float sq[256];
    __shared__ float sl[1024];
    __shared__ float red[8];
    __shared__ float s_b;
    int bm = blockIdx.x; int b = bm >> 5;
    int tid = threadIdx.x;
    sq[tid] = g_q[(size_t)bm * 256 + tid];
    __syncthreads();
    float lg[4]; float lmax = -3.4e38f;
    const float* kb = g_kk + ((size_t)b << 10) * 256;
    const float4* q4 = (const float4*)sq;
#pragma unroll
    for (int i = 0; i < 4; i++){
        const float4* kr = (const float4*)(kb + (size_t)(tid * 4 + i) * 256);
        float acc = 0.f;
#pragma unroll 8
        for (int d = 0; d < 64; d++){
            float4 k4 = kr[d], s4 = q4[d];
            acc = fmaf(s4.x,k4.x, fmaf(s4.y,k4.y, fmaf(s4.z,k4.z, fmaf(s4.w,k4.w, acc))));
        }
        lg[i] = acc * 0.0625f;
        lmax = fmaxf(lmax, lg[i]);
    }
    for (int o = 16; o; o >>= 1) lmax = fmaxf(lmax, __shfl_xor_sync(0xffffffffu, lmax, o));
    if ((tid & 31) == 0) red[tid >> 5] = lmax;
    __syncthreads();
    if (tid < 8){
        float t2 = red[tid];
        for (int o = 4; o; o >>= 1) t2 = fmaxf(t2, __shfl_xor_sync(0xffu, t2, o));
        if (tid == 0) s_b = t2;
    }
    __syncthreads();
    float bmax = s_b, lsum = 0.f;
#pragma unroll
    for (int i = 0; i < 4; i++){
        float e = expf(lg[i] - bmax);
        sl[tid * 4 + i] = e; lsum += e;
    }
    for (int o = 16; o; o >>= 1) lsum += __shfl_xor_sync(0xffffffffu, lsum, o);
    if ((tid & 31) == 0) red[tid >> 5] = lsum;
    __syncthreads();
    if (tid < 8){
        float t2 = red[tid];
        for (int o = 4; o; o >>= 1) t2 += __shfl_xor_sync(0xffu, t2, o);
        if (tid == 0) s_b = t2;
    }
    __syncthreads();
    float inv = 1.f / s_b;
    float acc = 0.f;
    const float* vb = g_v + ((size_t)b << 10) * 256 + tid;
    for (int s = 0; s < 1024; s++) acc = fmaf(sl[s], vb[(size_t)s * 256], acc);
    g_av[(size_t)bm * 256 + tid] = acc * inv;
}

// ------------------------- MHA (B=8, H=4, M=32, hd=64) -------------------------
__global__ void mha_kernel(){
    int bh = blockIdx.x; int b = bh >> 2, h = bh & 3;
    __shared__ float sq[32][65], sk[32][65], sv[32][65];
    __shared__ float sc[32][33];
    int tid = threadIdx.x;
    const float* base = g_qkvb + (size_t)b * 32 * 768 + h * 64;
    for (int i = tid; i < 2048; i += 256){
        int m = i >> 6, d = i & 63;
        sq[m][d] = base[(size_t)m * 768 + d];
        sk[m][d] = base[(size_t)m * 768 + 256 + d];
        sv[m][d] = base[(size_t)m * 768 + 512 + d];
    }
    __syncthreads();
    for (int p = tid; p < 1024; p += 256){
        int m = p >> 5, n = p & 31;
        float a = 0.f;
#pragma unroll
        for (int d = 0; d < 64; d++) a = fmaf(sq[m][d], sk[n][d], a);
        sc[m][n] = a * 0.125f;
    }
    __syncthreads();
    if (tid < 32){
        float mx = -3.4e38f;
        for (int n = 0; n < 32; n++) mx = fmaxf(mx, sc[tid][n]);
        float s = 0.f;
        for (int n = 0; n < 32; n++){ float e = expf(sc[tid][n] - mx); sc[tid][n] = e; s += e; }
        float inv = 1.f / s;
        for (int n = 0; n < 32; n++) sc[tid][n] *= inv;
    }
    __syncthreads();
    for (int p = tid; p < 2048; p += 256){
        int m = p >> 6, d = p & 63;
        float a = 0.f;
#pragma unroll
        for (int n = 0; n < 32; n++) a = fmaf(sc[m][n], sv[n][d], a);
        g_mo[((size_t)(b * 32 + m)) * 256 + h * 64 + d] = a;
    }
}

// ------------------------- LayerNorm (rows of 256) -----------------------------
__global__ void lnorm_kernel(int in_id, int out_id,
                             const float* __restrict__ g, const float* __restrict__ b){
    const float* in = buf_ptr(in_id);
    float* out = buf_ptr(out_id);
    int r = blockIdx.x, tid = threadIdx.x;
    __shared__ float red[8];
    __shared__ float s_mu, s_rv;
    float v = in[(size_t)r * 256 + tid];
    float s = v;
    for (int o = 16; o; o >>= 1) s += __shfl_xor_sync(0xffffffffu, s, o);
    if ((tid & 31) == 0) red[tid >> 5] = s;
    __syncthreads();
    if (tid < 8){
        float t2 = red[tid];
        for (int o = 4; o; o >>= 1) t2 += __shfl_xor_sync(0xffu, t2, o);
        if (tid == 0) s_mu = t2 * (1.f / 256.f);
    }
    __syncthreads();
    float mu = s_mu;
    float d = v - mu;
    float s2 = d * d;
    for (int o = 16; o; o >>= 1) s2 += __shfl_xor_sync(0xffffffffu, s2, o);
    if ((tid & 31) == 0) red[tid >> 5] = s2;
    __syncthreads();
    if (tid < 8){
        float t2 = red[tid];
        for (int o = 4; o; o >>= 1) t2 += __shfl_xor_sync(0xffu, t2, o);
        if (tid == 0) s_rv = rsqrtf(t2 * (1.f / 256.f) + 1e-5f);
    }
    __syncthreads();
    out[(size_t)r * 256 + tid] = d * s_rv * g[tid] + b[tid];
}

// ------------------------- host launcher ---------------------------------------
extern "C" void kernel_launch(void* const* d_in, const int* in_sizes, int n_in,
                              void* d_out, int out_size) {
    const float* xyz  = (const float*)d_in[0];
    const float* x    = (const float*)d_in[1];
    const float* t    = (const float*)d_in[2];
    const int*   far0 = (const int*)  d_in[3];
    const float* Wproj=(const float*)d_in[4];  const float* gproj=(const float*)d_in[5];  const float* bproj=(const float*)d_in[6];
    const float* Wl1 =(const float*)d_in[7];   const float* gl1 =(const float*)d_in[8];   const float* bl1 =(const float*)d_in[9];
    const float* Wl2 =(const float*)d_in[10];  const float* gl2 =(const float*)d_in[11];  const float* bl2 =(const float*)d_in[12];
    const float* Wc1 =(const float*)d_in[13];  const float* gc1 =(const float*)d_in[14];  const float* bc1 =(const float*)d_in[15];
    const float* Wc2 =(const float*)d_in[16];  const float* gc2 =(const float*)d_in[17];  const float* bc2 =(const float*)d_in[18];
    const float* Wq  =(const float*)d_in[19];  const float* Wk  =(const float*)d_in[20];
    const float* Wv  =(const float*)d_in[21];  const float* Wo  =(const float*)d_in[22];
    const float* ln1g=(const float*)d_in[23];  const float* ln1b=(const float*)d_in[24];
    const float* Wqkv=(const float*)d_in[25];  const float* Wao =(const float*)d_in[26];
    const float* ln2g=(const float*)d_in[27];  const float* ln2b=(const float*)d_in[28];
    const float* Wf1 =(const float*)d_in[29];  const float* Wf2 =(const float*)d_in[30];

    float* out   = (float*)d_out;
    float* o_nxyz= out;                         // [8,1024,3]   = 24576
    float* o_x   = out + 24576;                 // [8,256,1024] = 2097152
    float* o_t   = out + 24576 + 2097152;       // [8,32,256]   = 65536

    // pre-convert tensor-GEMM weights to fp16 (bit-identical to in-loader cvt)
    cvt_w_kernel<<<128, 256>>>(Wproj, WOFF_PROJ, 32768);
    cvt_w_kernel<<<256, 256>>>(Wl1, WOFF_L1, 65536);
    cvt_w_kernel<<<256, 256>>>(Wl2, WOFF_L2, 65536);
    cvt_w_kernel<<<256, 256>>>(Wc1, WOFF_C1, 65536);
    cvt_w_kernel<<<256, 256>>>(Wc2, WOFF_C2, 65536);
    cvt_w_kernel<<<256, 256>>>(Wk,  WOFF_K,  65536);
    cvt_w_kernel<<<256, 256>>>(Wv,  WOFF_V,  65536);

    transpose_x_kernel<<<dim3(128,4,8), dim3(32,32)>>>(x);
    gemm_tc<<<dim3(2, NPTS/128),256>>>(nullptr,ID_XT, nullptr,WOFF_PROJ, nullptr,ID_Y, 128, 256,
                                        nullptr, nullptr, nullptr,-1, 0, 0, 0, 0);
    fps_kernel<<<8, 1024>>>(xyz, far0, o_nxyz);
    knn_kernel<<<NGRP, 128>>>(o_nxyz, xyz);
    edge_kernel<<<NROWS/4, 256>>>(gproj, bproj);

    dim3 gBig(2, NROWS/128);
    gemm_tc<<<gBig,256>>>(nullptr,ID_H0, nullptr,WOFF_L1, nullptr,ID_R, 256, 256, gl1, bl1, nullptr,-1, 1, 1, 1, 0);
    gemm_tc<<<gBig,256>>>(nullptr,ID_R, nullptr,WOFF_L2, nullptr,ID_H0, 256, 256, gl2, bl2, nullptr,ID_H0, 1, 1, 1, 1);
    maxpool_kernel<<<NGRP, 256>>>();

    dim3 gGrp(2, NGRP/128);
    gemm_tc<<<gGrp,256>>>(nullptr,ID_F, nullptr,WOFF_C1, nullptr,ID_C1, 256, 256, gc1, bc1, nullptr,-1, 1, 0, 0, 0);
    gemm_tc<<<gGrp,256>>>(nullptr,ID_C1, nullptr,WOFF_C2, nullptr,ID_F2, 256, 256, gc2, bc2, nullptr,ID_F, 1, 0, 0, 0);
    transpose_f_kernel<<<dim3(32,8,8), dim3(32,32)>>>(o_x);

    dim3 gTok(4, 4);
    gemm_nt<<<gTok,256>>>(t,-1, Wq, nullptr,ID_Q, 256, 256, nullptr, nullptr, nullptr,-1, 0);
    gemm_tc<<<gGrp,256>>>(nullptr,ID_F2, nullptr,WOFF_K, nullptr,ID_KK, 256, 256, nullptr, nullptr, nullptr,-1, 0, 0, 0, 0);
    gemm_tc<<<gGrp,256>>>(nullptr,ID_F2, nullptr,WOFF_V, nullptr,ID_V, 256, 256, nullptr, nullptr, nullptr,-1, 0, 0, 0, 0);
    l2f_attn_kernel<<<256, 256>>>();
    gemm_nt<<<gTok,256>>>(nullptr,ID_AV, Wo, nullptr,ID_T1, 256, 256, nullptr, nullptr, t,-1, 0);

    lnorm_kernel<<<256, 256>>>(ID_T1, ID_HN, ln1g, ln1b);
    gemm_nt<<<dim3(12,4),256>>>(nullptr,ID_HN, Wqkv, nullptr,ID_QKVB, 256, 768, nullptr, nullptr, nullptr,-1, 0);
    mha_kernel<<<32, 256>>>();
    gemm_nt<<<gTok,256>>>(nullptr,ID_MO, Wao, nullptr,ID_T2, 256, 256, nullptr, nullptr, nullptr,ID_T1, 0);
    lnorm_kernel<<<256, 256>>>(ID_T2, ID_HN, ln2g, ln2b);
    gemm_nt<<<dim3(8,4),256>>>(nullptr,ID_HN, Wf1, nullptr,ID_FF, 256, 512, nullptr, nullptr, nullptr,-1, 1);
    gemm_nt<<<gTok,256>>>(nullptr,ID_FF, Wf2, o_t,-1, 512, 256, nullptr, nullptr, nullptr,ID_T2, 0);
}

// round 15
// speedup vs baseline: 1.5038x; 1.5038x over previous
#include <cuda_runtime.h>
#include <cuda_bf16.h>
#include <cuda_fp16.h>
#include <math.h>

#define BB 8
#define NN 4096
#define CINC 128
#define COUTC 256
#define SSP 1024
#define KNB 24
#define TCHC 256
#define MTOK 32
#define NROWS (BB*SSP*KNB)     /* 196608 */
#define NGRP  (BB*SSP)         /* 8192 */
#define NPTS  (BB*NN)          /* 32768 */
#define BN_SCALE 0.9999950000374997f

// ------------------------- device scratch ------------------------------------
__device__ float  g_xT[(size_t)BB*NN*CINC];
__device__ int    g_fps[BB*SSP];
__device__ int    g_knn[NROWS];
__device__ float  g_y [(size_t)NPTS*COUTC];
__device__ __half g_h0h[(size_t)NROWS*COUTC];
__device__ __half g_rh [(size_t)NROWS*COUTC];
__device__ float  g_f [(size_t)NGRP*COUTC];
__device__ float  g_c1[(size_t)NGRP*COUTC];
__device__ float  g_f2[(size_t)NGRP*COUTC];
__device__ float  g_kk[(size_t)NGRP*TCHC];
__device__ float  g_v [(size_t)NGRP*TCHC];
__device__ float  g_q [BB*MTOK*TCHC];
__device__ float  g_av[BB*MTOK*TCHC];
__device__ float  g_t1[BB*MTOK*TCHC];
__device__ float  g_hn[BB*MTOK*TCHC];
__device__ float  g_qkvb[BB*MTOK*3*TCHC];
__device__ float  g_mo[BB*MTOK*TCHC];
__device__ float  g_t2[BB*MTOK*TCHC];
__device__ float  g_ff[BB*MTOK*2*TCHC];

#define ID_H0 0
#define ID_R 1
#define ID_F 2
#define ID_C1 3
#define ID_F2 4
#define ID_KK 5
#define ID_V 6
#define ID_Q 7
#define ID_AV 8
#define ID_T1 9
#define ID_HN 10
#define ID_QKVB 11
#define ID_MO 12
#define ID_T2 13
#define ID_FF 14
#define ID_Y 15
#define ID_XT 16

__device__ __forceinline__ float* buf_ptr(int id){
    switch(id){
        case ID_F:  return g_f;    case ID_C1: return g_c1;
        case ID_F2: return g_f2;   case ID_KK: return g_kk;
        case ID_V:  return g_v;    case ID_Q:  return g_q;
        case ID_AV: return g_av;   case ID_T1: return g_t1;
        case ID_HN: return g_hn;   case ID_QKVB: return g_qkvb;
        case ID_MO: return g_mo;   case ID_T2: return g_t2;
        case ID_FF: return g_ff;   case ID_Y:  return g_y;
        case ID_XT: return g_xT;
    }
    return nullptr;
}
__device__ __forceinline__ __half* buf_ptr_h(int id){
    if (id == ID_H0) return g_h0h;
    if (id == ID_R)  return g_rh;
    return nullptr;
}

__device__ __forceinline__ float gelu_f(float x){
    return 0.5f * x * (1.0f + erff(x * 0.7071067811865476f));
}

__device__ __forceinline__ void mma_f16(float* d, const unsigned* a, const unsigned* b){
    asm volatile(
        "mma.sync.aligned.m16n8k16.row.col.f32.f16.f16.f32 "
        "{%0,%1,%2,%3}, {%4,%5,%6,%7}, {%8,%9}, {%0,%1,%2,%3};\n"
        : "+f"(d[0]), "+f"(d[1]), "+f"(d[2]), "+f"(d[3])
        : "r"(a[0]), "r"(a[1]), "r"(a[2]), "r"(a[3]), "r"(b[0]), "r"(b[1]));
}

// ------------------------- transpose x [B,128,4096]->[B,4096,128] -------------
__global__ void transpose_x_kernel(const float* __restrict__ x){
    __shared__ float tile[32][33];
    int n0 = blockIdx.x << 5, c0 = blockIdx.y << 5, b = blockIdx.z;
    int tx = threadIdx.x, ty = threadIdx.y;
    tile[ty][tx] = x[((size_t)(b*CINC + c0 + ty)) * NN + n0 + tx];
    __syncthreads();
    g_xT[((size_t)((b << 12) + n0 + ty)) * CINC + c0 + tx] = tile[tx][ty];
}

// ------------------------- FPS ------------------------------------------------
__global__ void fps_kernel(const float* __restrict__ xyz, const int* __restrict__ far0,
                           float* __restrict__ onxyz){
    __shared__ unsigned sd[32];
    __shared__ int      si[32];
    __shared__ float c3[3];
    __shared__ int s_far;
    int b = blockIdx.x, tid = threadIdx.x;
    int lane = tid & 31, w = tid >> 5;
    float px[4], py[4], pz[4], dmin[4];
#pragma unroll
    for (int i = 0; i < 4; i++){
        int j = (i << 10) + tid;
        const float* p = xyz + ((size_t)((b << 12) + j)) * 3;
        px[i] = p[0]; py[i] = p[1]; pz[i] = p[2];
        dmin[i] = 1e10f;
    }
    if (tid == 0){
        int f = far0[b]; s_far = f;
        const float* p = xyz + ((size_t)((b << 12) + f)) * 3;
        c3[0] = p[0]; c3[1] = p[1]; c3[2] = p[2];
    }
    __syncthreads();
    for (int it = 0; it < SSP; it++){
        float cx = c3[0], cy = c3[1], cz = c3[2];
        if (tid == 0){
            g_fps[(b << 10) + it] = s_far;
            float* o = onxyz + ((size_t)((b << 10) + it)) * 3;
            o[0] = cx; o[1] = cy; o[2] = cz;
        }
        unsigned um = 0u;
#pragma unroll
        for (int i = 0; i < 4; i++){
            float dx = px[i] - cx, dy = py[i] - cy, dz = pz[i] - cz;
            float d = dx*dx + dy*dy + dz*dz;
            dmin[i] = fminf(dmin[i], d);
            unsigned u = __float_as_uint(dmin[i]);
            if (u > um) um = u;
        }
        unsigned wm = __reduce_max_sync(0xffffffffu, um);
        int cand = 0x7FFFFFFF;
#pragma unroll
        for (int i = 0; i < 4; i++){
            if (__float_as_uint(dmin[i]) == wm){
                int j = (i << 10) + tid;
                if (j < cand) cand = j;
            }
        }
        int wj = (int)__reduce_min_sync(0xffffffffu, (unsigned)cand);
        if (lane == 0){ sd[w] = wm; si[w] = wj; }
        __syncthreads();
        if (tid < 32){
            unsigned v = sd[tid]; int idx = si[tid];
            unsigned m = __reduce_max_sync(0xffffffffu, v);
            int c2 = (v == m) ? idx : 0x7FFFFFFF;
            int nf = (int)__reduce_min_sync(0xffffffffu, (unsigned)c2);
            if (tid == 0){
                s_far = nf;
                const float* p = xyz + ((size_t)((b << 12) + nf)) * 3;
                c3[0] = p[0]; c3[1] = p[1]; c3[2] = p[2];
            }
        }
        __syncthreads();
    }
}

// ------------------------- KNN: REDUX top-24 with grouped rescan ---------------
__global__ void knn_kernel(const float* __restrict__ nxyz, const float* __restrict__ xyz){
    int cid = blockIdx.x, tid = threadIdx.x;
    int lane = tid & 31, w = tid >> 5;
    int b = cid >> 10;
    float cx = nxyz[(size_t)cid*3+0], cy = nxyz[(size_t)cid*3+1], cz = nxyz[(size_t)cid*3+2];
    float d[32];
#pragma unroll
    for (int i = 0; i < 32; i++){
        int j = (w << 10) + (i << 5) + lane;
        const float* p = xyz + ((size_t)((b << 12) + j)) * 3;
        float dx = p[0]-cx, dy = p[1]-cy, dz = p[2]-cz;
        d[i] = dx*dx + dy*dy + dz*dz;
    }
    __shared__ unsigned cd[4*KNB];
    __shared__ int      ci[4*KNB];

    float gm[4]; int gi[4];
#pragma unroll
    for (int g = 0; g < 4; g++){
        gm[g] = 3.4e38f; gi[g] = g*8;
#pragma unroll
        for (int k = 0; k < 8; k++){
            int i = g*8 + k;
            if (d[i] < gm[g]){ gm[g] = d[i]; gi[g] = i; }
        }
    }
    unsigned consumed = 0u;
#pragma unroll 1
    for (int r = 0; r < KNB; r++){
        float bd = gm[0]; int bi = gi[0];
        if (gm[1] < bd){ bd = gm[1]; bi = gi[1]; }
        if (gm[2] < bd){ bd = gm[2]; bi = gi[2]; }
        if (gm[3] < bd){ bd = gm[3]; bi = gi[3]; }
        unsigned dbits = __float_as_uint(bd);
        unsigned wmin = __reduce_min_sync(0xffffffffu, dbits);
        int myidx = (dbits == wmin) ? ((w << 10) + (bi << 5) + lane) : 0x7FFFFFFF;
        int widx = (int)__reduce_min_sync(0xffffffffu, (unsigned)myidx);
        if (lane == 0){ cd[w*KNB + r] = wmin; ci[w*KNB + r] = widx; }
        if (myidx == widx){
            consumed |= 1u << bi;
            int g = bi >> 3;
            if (g == 0){
                gm[0] = 3.4e38f; gi[0] = 0;
#pragma unroll
                for (int k = 0; k < 8; k++)
                    if (!((consumed >> k) & 1u) && d[k] < gm[0]){ gm[0] = d[k]; gi[0] = k; }
            } else if (g == 1){
                gm[1] = 3.4e38f; gi[1] = 8;
#pragma unroll
                for (int k = 8; k < 16; k++)
                    if (!((consumed >> k) & 1u) && d[k] < gm[1]){ gm[1] = d[k]; gi[1] = k; }
            } else if (g == 2){
                gm[2] = 3.4e38f; gi[2] = 16;
#pragma unroll
                for (int k = 16; k < 24; k++)
                    if (!((consumed >> k) & 1u) && d[k] < gm[2]){ gm[2] = d[k]; gi[2] = k; }
            } else {
                gm[3] = 3.4e38f; gi[3] = 24;
#pragma unroll
                for (int k = 24; k < 32; k++)
                    if (!((consumed >> k) & 1u) && d[k] < gm[3]){ gm[3] = d[k]; gi[3] = k; }
            }
        }
    }
    __syncthreads();

    if (w == 0){
        unsigned kd[3]; int ki[3];
#pragma unroll
        for (int s = 0; s < 3; s++){ kd[s] = cd[lane + 32*s]; ki[s] = ci[lane + 32*s]; }
#pragma unroll 1
        for (int r = 0; r < KNB; r++){
            unsigned lmd = kd[0]; int lmi = ki[0];
            if (kd[1] < lmd || (kd[1] == lmd && ki[1] < lmi)){ lmd = kd[1]; lmi = ki[1]; }
            if (kd[2] < lmd || (kd[2] == lmd && ki[2] < lmi)){ lmd = kd[2]; lmi = ki[2]; }
            unsigned wmin = __reduce_min_sync(0xffffffffu, lmd);
            int myidx = (lmd == wmin) ? lmi : 0x7FFFFFFF;
            int widx = (int)__reduce_min_sync(0xffffffffu, (unsigned)myidx);
            if (lane == 0) g_knn[(size_t)cid*KNB + r] = widx;
#pragma unroll
            for (int s = 0; s < 3; s++)
                if (ki[s] == widx){ kd[s] = 0xFFFFFFFFu; ki[s] = 0x7FFFFFFF; }
        }
    }
}

// ------------------------- edge combine: h0 = fp16(gelu(bn(y[nbr]-y[ctr]))) ----
__global__ void edge_kernel(const float* __restrict__ gproj, const float* __restrict__ bproj){
    int r = blockIdx.x * 4 + (threadIdx.x >> 6);
    int c4 = threadIdx.x & 63;
    int cid = r / KNB;
    int b = cid >> 10;
    int nbr = (b << 12) + g_knn[r];
    int ctr = (b << 12) + g_fps[cid];
    float4 a = ((const float4*)(g_y + (size_t)nbr * COUTC))[c4];
    float4 cc = ((const float4*)(g_y + (size_t)ctr * COUTC))[c4];
    int c = c4 << 2;
    float4 ga = *(const float4*)(gproj + c);
    float4 be = *(const float4*)(bproj + c);
    float o0 = gelu_f(fmaf(a.x - cc.x, ga.x * BN_SCALE, be.x));
    float o1 = gelu_f(fmaf(a.y - cc.y, ga.y * BN_SCALE, be.y));
    float o2 = gelu_f(fmaf(a.z - cc.z, ga.z * BN_SCALE, be.z));
    float o3 = gelu_f(fmaf(a.w - cc.w, ga.w * BN_SCALE, be.w));
    __half2* dst = (__half2*)(g_h0h + (size_t)r * COUTC + c);
    dst[0] = __floats2half2_rn(o0, o1);
    dst[1] = __floats2half2_rn(o2, o3);
}

// ------------------------- fp16 tensor-core NT GEMM ----------------------------
#define HST 24
__global__ void __launch_bounds__(256)
gemm_tc(const float* __restrict__ Aext, int Aid,
        const float* __restrict__ W,
        float* __restrict__ Cext, int Cid,
        int Kdim, int Ncols,
        const float* __restrict__ gamma, const float* __restrict__ beta,
        const float* __restrict__ resext, int resid,
        int act, int a_half, int c_half, int res_half)
{
    __shared__ __align__(16) __half As[2][128][HST];
    __shared__ __align__(16) __half Bs[2][128][HST];
    const float* A = (Aid >= 0 && !a_half) ? buf_ptr(Aid) : Aext;
    const __half* Ah = a_half ? buf_ptr_h(Aid) : nullptr;
    float* C = (Cid >= 0 && !c_half) ? buf_ptr(Cid) : Cext;
    __half* Ch = c_half ? buf_ptr_h(Cid) : nullptr;
    const float* res = (resid >= 0 && !res_half) ? buf_ptr(resid) : resext;
    const __half* resh = res_half ? buf_ptr_h(resid) : nullptr;

    const int tid = threadIdx.x;
    const int r0 = blockIdx.y * 128;
    const int n0 = blockIdx.x * 128;

    const int arow = tid >> 1;
    const int ak0  = (tid & 1) * 8;
    const float* pA = a_half ? nullptr : (A + (size_t)(r0 + arow) * Kdim + ak0);
    const __half* pAh = a_half ? (Ah + (size_t)(r0 + arow) * Kdim + ak0) : nullptr;
    const float* pW = W + (size_t)(n0 + arow) * Kdim + ak0;

    const int wid = tid >> 5, lane = tid & 31;
    const int wm0 = (wid & 1) * 64;
    const int wn0 = (wid >> 1) * 32;
    const int lr = lane >> 2;
    const int lc = lane & 3;

    float acc[4][4][4];
#pragma unroll
    for (int i = 0; i < 4; i++)
#pragma unroll
        for (int j = 0; j < 4; j++)
#pragma unroll
            for (int v = 0; v < 4; v++) acc[i][j][v] = 0.f;

    const int KT = Kdim >> 4;

    {
        unsigned* da = (unsigned*)&As[0][arow][ak0];
        if (a_half){
            uint4 v = *(const uint4*)(pAh);
            da[0] = v.x; da[1] = v.y; da[2] = v.z; da[3] = v.w;
        } else {
            float4 a0 = *(const float4*)(pA), a1 = *(const float4*)(pA + 4);
            __half2* dh = (__half2*)da;
            dh[0] = __floats2half2_rn(a0.x, a0.y); dh[1] = __floats2half2_rn(a0.z, a0.w);
            dh[2] = __floats2half2_rn(a1.x, a1.y); dh[3] = __floats2half2_rn(a1.z, a1.w);
        }
        float4 b0 = *(const float4*)(pW), b1 = *(const float4*)(pW + 4);
        __half2* db = (__half2*)&Bs[0][arow][ak0];
        db[0] = __floats2half2_rn(b0.x, b0.y); db[1] = __floats2half2_rn(b0.z, b0.w);
        db[2] = __floats2half2_rn(b1.x, b1.y); db[3] = __floats2half2_rn(b1.z, b1.w);
    }
    __syncthreads();

    for (int kt = 0; kt < KT; kt++){
        int p = kt & 1;
        float4 na0, na1, nb0, nb1;
        uint4 nah;
        bool more = (kt + 1 < KT);
        if (more){
            int ko = (kt + 1) << 4;
            if (a_half) nah = *(const uint4*)(pAh + ko);
            else { na0 = *(const float4*)(pA + ko); na1 = *(const float4*)(pA + ko + 4); }
            nb0 = *(const float4*)(pW + ko); nb1 = *(const float4*)(pW + ko + 4);
        }
        {
            unsigned afr[4][4], bfr[4][2];
#pragma unroll
            for (int mt = 0; mt < 4; mt++){
                int r = wm0 + mt*16 + lr;
                afr[mt][0] = *(const unsigned*)&As[p][r][2*lc];
                afr[mt][1] = *(const unsigned*)&As[p][r+8][2*lc];
                afr[mt][2] = *(const unsigned*)&As[p][r][2*lc+8];
                afr[mt][3] = *(const unsigned*)&As[p][r+8][2*lc+8];
            }
#pragma unroll
            for (int nt = 0; nt < 4; nt++){
                int n = wn0 + nt*8 + lr;
                bfr[nt][0] = *(const unsigned*)&Bs[p][n][2*lc];
                bfr[nt][1] = *(const unsigned*)&Bs[p][n][2*lc+8];
            }
#pragma unroll
            for (int mt = 0; mt < 4; mt++)
#pragma unroll
                for (int nt = 0; nt < 4; nt++)
                    mma_f16(acc[mt][nt], afr[mt], bfr[nt]);
        }
        if (more){
            int q = 1 - p;
            unsigned* da = (unsigned*)&As[q][arow][ak0];
            if (a_half){
                da[0] = nah.x; da[1] = nah.y; da[2] = nah.z; da[3] = nah.w;
            } else {
                __half2* dh = (__half2*)da;
                dh[0] = __floats2half2_rn(na0.x, na0.y); dh[1] = __floats2half2_rn(na0.z, na0.w);
                dh[2] = __floats2half2_rn(na1.x, na1.y); dh[3] = __floats2half2_rn(na1.z, na1.w);
            }
            __half2* db = (__half2*)&Bs[q][arow][ak0];
            db[0] = __floats2half2_rn(nb0.x, nb0.y); db[1] = __floats2half2_rn(nb0.z, nb0.w);
            db[2] = __floats2half2_rn(nb1.x, nb1.y); db[3] = __floats2half2_rn(nb1.z, nb1.w);
        }
        __syncthreads();
    }

#pragma unroll
    for (int mt = 0; mt < 4; mt++){
#pragma unroll
        for (int nt = 0; nt < 4; nt++){
            int cb = n0 + wn0 + nt*8 + lc*2;
            float ga0 = 0.f, ga1 = 0.f, be0 = 0.f, be1 = 0.f;
            if (gamma){
                ga0 = gamma[cb] * BN_SCALE;   be0 = beta[cb];
                ga1 = gamma[cb+1] * BN_SCALE; be1 = beta[cb+1];
            }
#pragma unroll
            for (int half = 0; half < 2; half++){
                int r = r0 + wm0 + mt*16 + lr + half*8;
                float y0 = acc[mt][nt][half*2+0];
                float y1 = acc[mt][nt][half*2+1];
                if (gamma){ y0 = fmaf(y0, ga0, be0); y1 = fmaf(y1, ga1, be1); }
                if (res_half){
                    float2 rv = __half22float2(*(const __half2*)(resh + (size_t)r * Ncols + cb));
                    y0 += rv.x; y1 += rv.y;
                } else if (res){
                    y0 += res[(size_t)r * Ncols + cb];
                    y1 += res[(size_t)r * Ncols + cb + 1];
                }
                if (act){ y0 = gelu_f(y0); y1 = gelu_f(y1); }
                if (c_half){
                    *(__half2*)(Ch + (size_t)r * Ncols + cb) = __floats2half2_rn(y0, y1);
                } else {
                    C[(size_t)r * Ncols + cb]     = y0;
                    C[(size_t)r * Ncols + cb + 1] = y1;
                }
            }
        }
    }
}

// ------------------------- fp32 NT GEMM (small token GEMMs) --------------------
__global__ void gemm_nt(const float* __restrict__ Aext, int Aid,
                        const float* __restrict__ W,
                        float* __restrict__ Cext, int Cid,
                        int Kdim, int Ncols,
                        const float* __restrict__ gamma, const float* __restrict__ beta,
                        const float* __restrict__ resext, int resid,
                        int act)
{
    __shared__ __align__(16) float As[16][68];
    __shared__ __align__(16) float Ws[16][68];
    const float* A = (Aid >= 0) ? buf_ptr(Aid) : Aext;
    float* C = (Cid >= 0) ? buf_ptr(Cid) : Cext;
    const float* res = (resid >= 0) ? buf_ptr(resid) : resext;
    const int tid = threadIdx.x;
    const int r0 = blockIdx.y * 64;
    const int n0 = blockIdx.x * 64;
    const int lrow = tid >> 2;
    const int lk4  = (tid & 3) << 2;
    const float* pA = A + (size_t)(r0 + lrow) * Kdim + lk4;
    const float* pW = W + (size_t)(n0 + lrow) * Kdim + lk4;
    const int tm0 = (tid & 15) << 2;
    const int tn0 = (tid >> 4) << 2;
    float acc[4][4];
#pragma unroll
    for (int i = 0; i < 4; i++)
#pragma unroll
        for (int j = 0; j < 4; j++) acc[i][j] = 0.f;

    for (int k0 = 0; k0 < Kdim; k0 += 16){
        float4 av = *(const float4*)(pA + k0);
        float4 wv = *(const float4*)(pW + k0);
        __syncthreads();
        As[lk4+0][lrow]=av.x; As[lk4+1][lrow]=av.y; As[lk4+2][lrow]=av.z; As[lk4+3][lrow]=av.w;
        Ws[lk4+0][lrow]=wv.x; Ws[lk4+1][lrow]=wv.y; Ws[lk4+2][lrow]=wv.z; Ws[lk4+3][lrow]=wv.w;
        __syncthreads();
#pragma unroll
        for (int k = 0; k < 16; k++){
            float4 a4 = *(const float4*)&As[k][tm0];
            float4 w4 = *(const float4*)&Ws[k][tn0];
            acc[0][0]=fmaf(a4.x,w4.x,acc[0][0]); acc[0][1]=fmaf(a4.x,w4.y,acc[0][1]);
            acc[0][2]=fmaf(a4.x,w4.z,acc[0][2]); acc[0][3]=fmaf(a4.x,w4.w,acc[0][3]);
            acc[1][0]=fmaf(a4.y,w4.x,acc[1][0]); acc[1][1]=fmaf(a4.y,w4.y,acc[1][1]);
            acc[1][2]=fmaf(a4.y,w4.z,acc[1][2]); acc[1][3]=fmaf(a4.y,w4.w,acc[1][3]);
            acc[2][0]=fmaf(a4.z,w4.x,acc[2][0]); acc[2][1]=fmaf(a4.z,w4.y,acc[2][1]);
            acc[2][2]=fmaf(a4.z,w4.z,acc[2][2]); acc[2][3]=fmaf(a4.z,w4.w,acc[2][3]);
            acc[3][0]=fmaf(a4.w,w4.x,acc[3][0]); acc[3][1]=fmaf(a4.w,w4.y,acc[3][1]);
            acc[3][2]=fmaf(a4.w,w4.z,acc[3][2]); acc[3][3]=fmaf(a4.w,w4.w,acc[3][3]);
        }
    }
#pragma unroll
    for (int i = 0; i < 4; i++){
        int r = r0 + tm0 + i;
#pragma unroll
        for (int j = 0; j < 4; j++){
            int c = n0 + tn0 + j;
            float y = acc[i][j];
            if (gamma) y = fmaf(y, gamma[c] * BN_SCALE, beta[c]);
            if (res)   y += res[(size_t)r * Ncols + c];
            if (act)   y = gelu_f(y);
            C[(size_t)r * Ncols + c] = y;
        }
    }
}

// ------------------------- maxpool over K neighbors (half2 vectorized) ---------
__global__ void maxpool_kernel(){
    int gidx = blockIdx.x, c2 = threadIdx.x;          // 128 threads = 128 half2 pairs
    const __half2* p = (const __half2*)(g_h0h + (size_t)gidx * KNB * COUTC) + c2;
    float2 m = make_float2(-3.4e38f, -3.4e38f);
#pragma unroll
    for (int j = 0; j < KNB; j++){
        float2 v = __half22float2(p[j * (COUTC/2)]);
        m.x = fmaxf(m.x, v.x); m.y = fmaxf(m.y, v.y);
    }
    float2* dst = (float2*)(g_f + (size_t)gidx * COUTC) + c2;
    *dst = m;
}

// ------------------------- transpose f2 [B,S,C]->[B,C,S] into out --------------
__global__ void transpose_f_kernel(float* __restrict__ out){
    __shared__ float tile[32][33];
    int s0 = blockIdx.x << 5, c0 = blockIdx.y << 5, b = blockIdx.z;
    int tx = threadIdx.x, ty = threadIdx.y;
    tile[ty][tx] = g_f2[((size_t)((b << 10) + s0 + ty)) * COUTC + c0 + tx];
    __syncthreads();
    out[((size_t)(b * COUTC + c0 + ty) << 10) + s0 + tx] = tile[tx][ty];
}

// ------------------------- Local2Former cross-attention ------------------------
__global__ void l2f_attn_kernel(){
    __shared__ float sq[256];
    __shared__ float sl[1024];
    __shared__ float red[8];
    __shared__ float s_b;
    int bm = blockIdx.x; int b = bm >> 5;
    int tid = threadIdx.x;
    sq[tid] = g_q[(size_t)bm * 256 + tid];
    __syncthreads();
    float lg[4]; float lmax = -3.4e38f;
    const float* kb = g_kk + ((size_t)b << 10) * 256;
    const float4* q4 = (const float4*)sq;
#pragma unroll
    for (int i = 0; i < 4; i++){
        const float4* kr = (const float4*)(kb + (size_t)(tid * 4 + i) * 256);
        float acc = 0.f;
#pragma unroll 8
        for (int d = 0; d < 64; d++){
            float4 k4 = kr[d], s4 = q4[d];
            acc = fmaf(s4.x,k4.x, fmaf(s4.y,k4.y, fmaf(s4.z,k4.z, fmaf(s4.w,k4.w, acc))));
        }
        lg[i] = acc * 0.0625f;
        lmax = fmaxf(lmax, lg[i]);
    }
    for (int o = 16; o; o >>= 1) lmax = fmaxf(lmax, __shfl_xor_sync(0xffffffffu, lmax, o));
    if ((tid & 31) == 0) red[tid >> 5] = lmax;
    __syncthreads();
    if (tid < 8){
        float t2 = red[tid];
        for (int o = 4; o; o >>= 1) t2 = fmaxf(t2, __shfl_xor_sync(0xffu, t2, o));
        if (tid == 0) s_b = t2;
    }
    __syncthreads();
    float bmax = s_b, lsum = 0.f;
#pragma unroll
    for (int i = 0; i < 4; i++){
        float e = expf(lg[i] - bmax);
        sl[tid * 4 + i] = e; lsum += e;
    }
    for (int o = 16; o; o >>= 1) lsum += __shfl_xor_sync(0xffffffffu, lsum, o);
    if ((tid & 31) == 0) red[tid >> 5] = lsum;
    __syncthreads();
    if (tid < 8){
        float t2 = red[tid];
        for (int o = 4; o; o >>= 1) t2 += __shfl_xor_sync(0xffu, t2, o);
        if (tid == 0) s_b = t2;
    }
    __syncthreads();
    float inv = 1.f / s_b;
    float acc = 0.f;
    const float* vb = g_v + ((size_t)b << 10) * 256 + tid;
    for (int s = 0; s < 1024; s++) acc = fmaf(sl[s], vb[(size_t)s * 256], acc);
    g_av[(size_t)bm * 256 + tid] = acc * inv;
}

// ------------------------- MHA (B=8, H=4, M=32, hd=64) -------------------------
__global__ void mha_kernel(){
    int bh = blockIdx.x; int b = bh >> 2, h = bh & 3;
    __shared__ float sq[32][65], sk[32][65], sv[32][65];
    __shared__ float sc[32][33];
    int tid = threadIdx.x;
    const float* base = g_qkvb + (size_t)b * 32 * 768 + h * 64;
    for (int i = tid; i < 2048; i += 256){
        int m = i >> 6, d = i & 63;
        sq[m][d] = base[(size_t)m * 768 + d];
        sk[m][d] = base[(size_t)m * 768 + 256 + d];
        sv[m][d] = base[(size_t)m * 768 + 512 + d];
    }
    __syncthreads();
    for (int p = tid; p < 1024; p += 256){
        int m = p >> 5, n = p & 31;
        float a = 0.f;
#pragma unroll
        for (int d = 0; d < 64; d++) a = fmaf(sq[m][d], sk[n][d], a);
        sc[m][n] = a * 0.125f;
    }
    __syncthreads();
    if (tid < 32){
        float mx = -3.4e38f;
        for (int n = 0; n < 32; n++) mx = fmaxf(mx, sc[tid][n]);
        float s = 0.f;
        for (int n = 0; n < 32; n++){ float e = expf(sc[tid][n] - mx); sc[tid][n] = e; s += e; }
        float inv = 1.f / s;
        for (int n = 0; n < 32; n++) sc[tid][n] *= inv;
    }
    __syncthreads();
    for (int p = tid; p < 2048; p += 256){
        int m = p >> 6, d = p & 63;
        float a = 0.f;
#pragma unroll
        for (int n = 0; n < 32; n++) a = fmaf(sc[m][n], sv[n][d], a);
        g_mo[((size_t)(b * 32 + m)) * 256 + h * 64 + d] = a;
    }
}

// ------------------------- LayerNorm (rows of 256) -----------------------------
__global__ void lnorm_kernel(int in_id, int out_id,
                             const float* __restrict__ g, const float* __restrict__ b){
    const float* in = buf_ptr(in_id);
    float* out = buf_ptr(out_id);
    int r = blockIdx.x, tid = threadIdx.x;
    __shared__ float red[8];
    __shared__ float s_mu, s_rv;
    float v = in[(size_t)r * 256 + tid];
    float s = v;
    for (int o = 16; o; o >>= 1) s += __shfl_xor_sync(0xffffffffu, s, o);
    if ((tid & 31) == 0) red[tid >> 5] = s;
    __syncthreads();
    if (tid < 8){
        float t2 = red[tid];
        for (int o = 4; o; o >>= 1) t2 += __shfl_xor_sync(0xffu, t2, o);
        if (tid == 0) s_mu = t2 * (1.f / 256.f);
    }
    __syncthreads();
    float mu = s_mu;
    float d = v - mu;
    float s2 = d * d;
    for (int o = 16; o; o >>= 1) s2 += __shfl_xor_sync(0xffffffffu, s2, o);
    if ((tid & 31) == 0) red[tid >> 5] = s2;
    __syncthreads();
    if (tid < 8){
        float t2 = red[tid];
        for (int o = 4; o; o >>= 1) t2 += __shfl_xor_sync(0xffu, t2, o);
        if (tid == 0) s_rv = rsqrtf(t2 * (1.f / 256.f) + 1e-5f);
    }
    __syncthreads();
    out[(size_t)r * 256 + tid] = d * s_rv * g[tid] + b[tid];
}

// ------------------------- host launcher ---------------------------------------
extern "C" void kernel_launch(void* const* d_in, const int* in_sizes, int n_in,
                              void* d_out, int out_size) {
    const float* xyz  = (const float*)d_in[0];
    const float* x    = (const float*)d_in[1];
    const float* t    = (const float*)d_in[2];
    const int*   far0 = (const int*)  d_in[3];
    const float* Wproj=(const float*)d_in[4];  const float* gproj=(const float*)d_in[5];  const float* bproj=(const float*)d_in[6];
    const float* Wl1 =(const float*)d_in[7];   const float* gl1 =(const float*)d_in[8];   const float* bl1 =(const float*)d_in[9];
    const float* Wl2 =(const float*)d_in[10];  const float* gl2 =(const float*)d_in[11];  const float* bl2 =(const float*)d_in[12];
    const float* Wc1 =(const float*)d_in[13];  const float* gc1 =(const float*)d_in[14];  const float* bc1 =(const float*)d_in[15];
    const float* Wc2 =(const float*)d_in[16];  const float* gc2 =(const float*)d_in[17];  const float* bc2 =(const float*)d_in[18];
    const float* Wq  =(const float*)d_in[19];  const float* Wk  =(const float*)d_in[20];
    const float* Wv  =(const float*)d_in[21];  const float* Wo  =(const float*)d_in[22];
    const float* ln1g=(const float*)d_in[23];  const float* ln1b=(const float*)d_in[24];
    const float* Wqkv=(const float*)d_in[25];  const float* Wao =(const float*)d_in[26];
    const float* ln2g=(const float*)d_in[27];  const float* ln2b=(const float*)d_in[28];
    const float* Wf1 =(const float*)d_in[29];  const float* Wf2 =(const float*)d_in[30];

    float* out   = (float*)d_out;
    float* o_nxyz= out;                         // [8,1024,3]   = 24576
    float* o_x   = out + 24576;                 // [8,256,1024] = 2097152
    float* o_t   = out + 24576 + 2097152;       // [8,32,256]   = 65536

    transpose_x_kernel<<<dim3(128,4,8), dim3(32,32)>>>(x);
    gemm_tc<<<dim3(2, NPTS/128),256>>>(nullptr,ID_XT, Wproj, nullptr,ID_Y, 128, 256,
                                        nullptr, nullptr, nullptr,-1, 0, 0, 0, 0);
    fps_kernel<<<8, 1024>>>(xyz, far0, o_nxyz);
    knn_kernel<<<NGRP, 128>>>(o_nxyz, xyz);
    edge_kernel<<<NROWS/4, 256>>>(gproj, bproj);

    dim3 gBig(2, NROWS/128);
    gemm_tc<<<gBig,256>>>(nullptr,ID_H0, Wl1, nullptr,ID_R, 256, 256, gl1, bl1, nullptr,-1, 1, 1, 1, 0);
    gemm_tc<<<gBig,256>>>(nullptr,ID_R, Wl2, nullptr,ID_H0, 256, 256, gl2, bl2, nullptr,ID_H0, 1, 1, 1, 1);
    maxpool_kernel<<<NGRP, 128>>>();

    dim3 gGrp(2, NGRP/128);
    gemm_tc<<<gGrp,256>>>(nullptr,ID_F, Wc1, nullptr,ID_C1, 256, 256, gc1, bc1, nullptr,-1, 1, 0, 0, 0);
    gemm_tc<<<gGrp,256>>>(nullptr,ID_C1, Wc2, nullptr,ID_F2, 256, 256, gc2, bc2, nullptr,ID_F, 1, 0, 0, 0);
    transpose_f_kernel<<<dim3(32,8,8), dim3(32,32)>>>(o_x);

    dim3 gTok(4, 4);
    gemm_nt<<<gTok,256>>>(t,-1, Wq, nullptr,ID_Q, 256, 256, nullptr, nullptr, nullptr,-1, 0);
    gemm_tc<<<gGrp,256>>>(nullptr,ID_F2, Wk, nullptr,ID_KK, 256, 256, nullptr, nullptr, nullptr,-1, 0, 0, 0, 0);
    gemm_tc<<<gGrp,256>>>(nullptr,ID_F2, Wv, nullptr,ID_V, 256, 256, nullptr, nullptr, nullptr,-1, 0, 0, 0, 0);
    l2f_attn_kernel<<<256, 256>>>();
    gemm_nt<<<gTok,256>>>(nullptr,ID_AV, Wo, nullptr,ID_T1, 256, 256, nullptr, nullptr, t,-1, 0);

    lnorm_kernel<<<256, 256>>>(ID_T1, ID_HN, ln1g, ln1b);
    gemm_nt<<<dim3(12,4),256>>>(nullptr,ID_HN, Wqkv, nullptr,ID_QKVB, 256, 768, nullptr, nullptr, nullptr,-1, 0);
    mha_kernel<<<32, 256>>>();
    gemm_nt<<<gTok,256>>>(nullptr,ID_MO, Wao, nullptr,ID_T2, 256, 256, nullptr, nullptr, nullptr,ID_T1, 0);
    lnorm_kernel<<<256, 256>>>(ID_T2, ID_HN, ln2g, ln2b);
    gemm_nt<<<dim3(8,4),256>>>(nullptr,ID_HN, Wf1, nullptr,ID_FF, 256, 512, nullptr, nullptr, nullptr,-1, 1);
    gemm_nt<<<gTok,256>>>(nullptr,ID_FF, Wf2, o_t,-1, 512, 256, nullptr, nullptr, nullptr,ID_T2, 0);
}